// round 1
// baseline (speedup 1.0000x reference)
#include <cuda_runtime.h>
#include <cuda_bf16.h>

// Shapes (fixed by the problem)
#define BSZ  8
#define CIN  512
#define COUT 512
#define SSZ  512
#define HDIM 64
#define WDIM 64

// conv tile config
#define TCO 128   // cout per block
#define TH  16    // spatial rows per block
#define TW  8     // spatial cols per block
#define CK  8     // cin chunk

// Scratch (device globals: allocation-free)
__device__ float g_s[BSZ * CIN];                 // modulation s[b,ci]
__device__ float g_g[BSZ * COUT];                // epilogue scale conv_scale*demod
__device__ float g_wsq[COUT * CIN];              // sum_k weight^2
__device__ float g_wt[CIN * 9 * COUT];           // weight transposed [ci][tap][co]

static __device__ __forceinline__ float warp_sum(float v) {
    #pragma unroll
    for (int o = 16; o; o >>= 1) v += __shfl_xor_sync(0xffffffffu, v, o);
    return v;
}

// s[b,ci] = sum_t style[b,t] * mod_weight[ci,t] * lin_scale + mod_bias[ci]
__global__ void k_style(const float* __restrict__ style,
                        const float* __restrict__ mod_weight,
                        const float* __restrict__ mod_bias,
                        float* __restrict__ out_tail) {
    int warp = (blockIdx.x * blockDim.x + threadIdx.x) >> 5;
    int lane = threadIdx.x & 31;
    if (warp >= BSZ * CIN) return;
    int b = warp >> 9, ci = warp & 511;
    const float* st = style + (size_t)b * SSZ;
    const float* mw = mod_weight + (size_t)ci * SSZ;
    float acc = 0.f;
    for (int t = lane; t < SSZ; t += 32) acc += st[t] * mw[t];
    acc = warp_sum(acc);
    if (lane == 0) {
        const float lin_scale = 0.044194173824159216f;  // 1/sqrt(512)
        float v = acc * lin_scale + mod_bias[ci];
        g_s[warp] = v;
        if (out_tail) out_tail[warp] = v;   // s5 flattened = s[b,ci]
    }
}

// Transpose weight to [ci][tap][co] and compute Wsq[co,ci] = sum_k w^2
__global__ void k_wprep(const float* __restrict__ weight) {
    int idx = blockIdx.x * blockDim.x + threadIdx.x;
    if (idx >= COUT * CIN) return;
    int co = idx >> 9, ci = idx & 511;
    const float* wp = weight + (size_t)idx * 9;
    float sq = 0.f;
    #pragma unroll
    for (int k = 0; k < 9; ++k) {
        float v = wp[k];
        sq += v * v;
        g_wt[(size_t)(ci * 9 + k) * COUT + co] = v;
    }
    g_wsq[(size_t)co * CIN + ci] = sq;
}

// g[b,co] = conv_scale * rsqrt(conv_scale^2 * sum_ci s^2 * Wsq + eps)
__global__ void k_demod() {
    int warp = (blockIdx.x * blockDim.x + threadIdx.x) >> 5;
    int lane = threadIdx.x & 31;
    if (warp >= BSZ * COUT) return;
    int b = warp >> 9, co = warp & 511;
    const float* sp = g_s + (size_t)b * CIN;
    const float* wq = g_wsq + (size_t)co * CIN;
    float acc = 0.f;
    for (int t = lane; t < CIN; t += 32) {
        float sv = sp[t];
        acc += sv * sv * wq[t];
    }
    acc = warp_sum(acc);
    if (lane == 0) {
        const float cs = 0.014731391274719742f;  // 1/sqrt(512*9)
        g_g[warp] = cs * rsqrtf(cs * cs * acc + 1e-8f);
    }
}

// Direct conv: block = (b, co-tile of 128, 16x8 spatial tile), 256 threads,
// 8x8 register micro-tile per thread, Cin chunks of 8, 9 taps unrolled.
__global__ __launch_bounds__(256, 2)
void k_conv(const float* __restrict__ x, float* __restrict__ out) {
    __shared__ float xs[CK * 18 * 10];     // 1440 floats: [ci_in][row 0..17][col 0..9]
    __shared__ float ws[CK * 9 * TCO];     // 9216 floats: [ci_in][tap][co]

    const int tid = threadIdx.x;
    const int tx = tid & 15;       // -> cout
    const int ty = tid >> 4;       // -> spatial
    const int b   = blockIdx.z;
    const int co0 = blockIdx.y * TCO;
    const int gr0 = (blockIdx.x >> 3) * TH;   // 4 row tiles
    const int gc0 = (blockIdx.x & 7) * TW;    // 8 col tiles
    const int r0 = ty >> 3;        // 0..1
    const int c0 = ty & 7;         // 0..7

    float acc[8][8];
    #pragma unroll
    for (int i = 0; i < 8; ++i)
        #pragma unroll
        for (int j = 0; j < 8; ++j) acc[i][j] = 0.f;

    const float* xb = x + (size_t)b * CIN * HDIM * WDIM;
    const float* sb = g_s + (size_t)b * CIN;

    for (int ci0 = 0; ci0 < CIN; ci0 += CK) {
        __syncthreads();
        // ---- load x tile (with halo), modulated by s[b,ci]
        for (int idx = tid; idx < CK * 180; idx += 256) {
            int cin = idx / 180;
            int rem = idx - cin * 180;
            int r = rem / 10;
            int c = rem - r * 10;
            int gh = gr0 + r - 1;
            int gw = gc0 + c - 1;
            float v = 0.f;
            if ((unsigned)gh < (unsigned)HDIM && (unsigned)gw < (unsigned)WDIM)
                v = xb[(size_t)(ci0 + cin) * (HDIM * WDIM) + gh * WDIM + gw] * sb[ci0 + cin];
            xs[idx] = v;
        }
        // ---- load weight tile [ci_in][tap][co] (coalesced from g_wt)
        {
            const float* wtp = g_wt + (size_t)ci0 * 9 * COUT + co0;
            for (int idx = tid; idx < CK * 9 * TCO; idx += 256) {
                int row = idx >> 7;        // ci_in*9 + tap
                int co_in = idx & 127;
                ws[idx] = wtp[(size_t)row * COUT + co_in];
            }
        }
        __syncthreads();

        #pragma unroll
        for (int kk = 0; kk < CK; ++kk) {
            const float* xp = xs + kk * 180 + r0 * 10 + c0;
            const float* wp = ws + kk * 9 * TCO + tx;
            #pragma unroll
            for (int tap = 0; tap < 9; ++tap) {
                const int dr = tap / 3;
                const int dc = tap - dr * 3;
                float xf[8], wf[8];
                #pragma unroll
                for (int i = 0; i < 8; ++i) xf[i] = xp[i * 20 + dr * 10 + dc];
                #pragma unroll
                for (int j = 0; j < 8; ++j) wf[j] = wp[tap * TCO + j * 16];
                #pragma unroll
                for (int i = 0; i < 8; ++i)
                    #pragma unroll
                    for (int j = 0; j < 8; ++j)
                        acc[i][j] = fmaf(xf[i], wf[j], acc[i][j]);
            }
        }
    }

    // ---- epilogue: demodulate and store
    #pragma unroll
    for (int j = 0; j < 8; ++j) {
        int co = co0 + tx + j * 16;
        float gm = g_g[(size_t)b * COUT + co];
        #pragma unroll
        for (int i = 0; i < 8; ++i) {
            int h = gr0 + r0 + 2 * i;
            int w = gc0 + c0;
            out[(((size_t)b * COUT + co) * HDIM + h) * WDIM + w] = acc[i][j] * gm;
        }
    }
}

extern "C" void kernel_launch(void* const* d_in, const int* in_sizes, int n_in,
                              void* d_out, int out_size) {
    const float* x          = (const float*)d_in[0];
    const float* style      = (const float*)d_in[1];
    const float* weight     = (const float*)d_in[2];
    const float* mod_weight = (const float*)d_in[3];
    const float* mod_bias   = (const float*)d_in[4];
    float* out = (float*)d_out;

    const long long conv_elems = (long long)BSZ * COUT * HDIM * WDIM;  // 16,777,216
    float* tail = (out_size >= conv_elems + BSZ * CIN) ? (out + conv_elems) : nullptr;

    k_style<<<(BSZ * CIN * 32) / 256, 256>>>(style, mod_weight, mod_bias, tail);
    k_wprep<<<(COUT * CIN) / 256, 256>>>(weight);
    k_demod<<<(BSZ * COUT * 32) / 256, 256>>>();

    dim3 grid((HDIM / TH) * (WDIM / TW), COUT / TCO, BSZ);  // (32, 4, 8)
    k_conv<<<grid, 256>>>(x, out);
}

// round 6
// speedup vs baseline: 1.3316x; 1.3316x over previous
#include <cuda_runtime.h>
#include <cuda_bf16.h>

// Shapes (fixed by the problem)
#define BSZ  8
#define CIN  512
#define COUT 512
#define SSZ  512
#define HDIM 64
#define WDIM 64

// conv tile config
#define TCO 128   // cout per block
#define TH  16    // spatial rows per block
#define TW  8     // spatial cols per block
#define CK  8     // cin chunk

// Scratch (device globals: allocation-free)
__device__ float g_s[BSZ * CIN];                 // modulation s[b,ci]
__device__ float g_g[BSZ * COUT];                // epilogue scale conv_scale*demod
__device__ float g_wsq[COUT * CIN];              // sum_k weight^2
__device__ float g_wt[CIN * 9 * COUT];           // weight transposed [ci][tap][co]

static __device__ __forceinline__ float warp_sum(float v) {
    #pragma unroll
    for (int o = 16; o; o >>= 1) v += __shfl_xor_sync(0xffffffffu, v, o);
    return v;
}

// ---- packed fp32x2 helpers (sm_103a FFMA2 path; ptxas never auto-fuses) ----
static __device__ __forceinline__ unsigned long long pack2(float lo, float hi) {
    unsigned long long r;
    asm("mov.b64 %0, {%1, %2};" : "=l"(r) : "f"(lo), "f"(hi));
    return r;
}
static __device__ __forceinline__ void fma2(unsigned long long& d,
                                            unsigned long long a,
                                            unsigned long long b) {
    asm("fma.rn.f32x2 %0, %1, %2, %0;" : "+l"(d) : "l"(a), "l"(b));
}
static __device__ __forceinline__ void unpack2(unsigned long long v, float& lo, float& hi) {
    asm("mov.b64 {%0, %1}, %2;" : "=f"(lo), "=f"(hi) : "l"(v));
}

// s[b,ci] = sum_t style[b,t] * mod_weight[ci,t] * lin_scale + mod_bias[ci]
__global__ void k_style(const float* __restrict__ style,
                        const float* __restrict__ mod_weight,
                        const float* __restrict__ mod_bias,
                        float* __restrict__ out_tail) {
    int warp = (blockIdx.x * blockDim.x + threadIdx.x) >> 5;
    int lane = threadIdx.x & 31;
    if (warp >= BSZ * CIN) return;
    int b = warp >> 9, ci = warp & 511;
    const float* st = style + (size_t)b * SSZ;
    const float* mw = mod_weight + (size_t)ci * SSZ;
    float acc = 0.f;
    for (int t = lane; t < SSZ; t += 32) acc += st[t] * mw[t];
    acc = warp_sum(acc);
    if (lane == 0) {
        const float lin_scale = 0.044194173824159216f;  // 1/sqrt(512)
        float v = acc * lin_scale + mod_bias[ci];
        g_s[warp] = v;
        if (out_tail) out_tail[warp] = v;   // s5 flattened = s[b,ci]
    }
}

// Transpose weight to [ci][tap][co] and compute Wsq[co,ci] = sum_k w^2
__global__ void k_wprep(const float* __restrict__ weight) {
    int idx = blockIdx.x * blockDim.x + threadIdx.x;
    if (idx >= COUT * CIN) return;
    int co = idx >> 9, ci = idx & 511;
    const float* wp = weight + (size_t)idx * 9;
    float sq = 0.f;
    #pragma unroll
    for (int k = 0; k < 9; ++k) {
        float v = wp[k];
        sq += v * v;
        g_wt[(size_t)(ci * 9 + k) * COUT + co] = v;
    }
    g_wsq[(size_t)co * CIN + ci] = sq;
}

// g[b,co] = conv_scale * rsqrt(conv_scale^2 * sum_ci s^2 * Wsq + eps)
__global__ void k_demod() {
    int warp = (blockIdx.x * blockDim.x + threadIdx.x) >> 5;
    int lane = threadIdx.x & 31;
    if (warp >= BSZ * COUT) return;
    int b = warp >> 9, co = warp & 511;
    const float* sp = g_s + (size_t)b * CIN;
    const float* wq = g_wsq + (size_t)co * CIN;
    float acc = 0.f;
    for (int t = lane; t < CIN; t += 32) {
        float sv = sp[t];
        acc += sv * sv * wq[t];
    }
    acc = warp_sum(acc);
    if (lane == 0) {
        const float cs = 0.014731391274719742f;  // 1/sqrt(512*9)
        g_g[warp] = cs * rsqrtf(cs * cs * acc + 1e-8f);
    }
}

// Direct conv with packed fp32x2 FMA.
// Block = (b, co-tile of 128, 16x8 spatial tile), 256 threads.
// Thread micro-tile: 8 spatial rows x 8 couts (4 adjacent pairs, packed f32x2).
// Weight pairs read as aligned LDS.64 (already packed); x broadcast-packed.
__global__ __launch_bounds__(256, 2)
void k_conv(const float* __restrict__ x, float* __restrict__ out) {
    __shared__ __align__(16) float xs[CK * 18 * 10];  // [ci_in][row 0..17][col 0..9]
    __shared__ __align__(16) float ws[CK * 9 * TCO];  // [ci_in][tap][co]

    const int tid = threadIdx.x;
    const int tx = tid & 15;       // -> cout pair base: co0 + jp*32 + tx*2
    const int ty = tid >> 4;       // -> spatial
    const int b   = blockIdx.z;
    const int co0 = blockIdx.y * TCO;
    const int gr0 = (blockIdx.x >> 3) * TH;   // 4 row tiles
    const int gc0 = (blockIdx.x & 7) * TW;    // 8 col tiles
    const int r0 = ty >> 3;        // 0..1
    const int c0 = ty & 7;         // 0..7

    unsigned long long acc2[8][4];
    #pragma unroll
    for (int i = 0; i < 8; ++i)
        #pragma unroll
        for (int jp = 0; jp < 4; ++jp) acc2[i][jp] = 0ull;

    const float* xb = x + (size_t)b * CIN * HDIM * WDIM;
    const float* sb = g_s + (size_t)b * CIN;

    for (int ci0 = 0; ci0 < CIN; ci0 += CK) {
        __syncthreads();
        // ---- load x tile (with halo), modulated by s[b,ci]
        for (int idx = tid; idx < CK * 180; idx += 256) {
            int cin = idx / 180;
            int rem = idx - cin * 180;
            int r = rem / 10;
            int c = rem - r * 10;
            int gh = gr0 + r - 1;
            int gw = gc0 + c - 1;
            float v = 0.f;
            if ((unsigned)gh < (unsigned)HDIM && (unsigned)gw < (unsigned)WDIM)
                v = xb[(size_t)(ci0 + cin) * (HDIM * WDIM) + gh * WDIM + gw] * sb[ci0 + cin];
            xs[idx] = v;
        }
        // ---- load weight tile [ci_in][tap][co] (coalesced from g_wt)
        {
            const float* wtp = g_wt + (size_t)ci0 * 9 * COUT + co0;
            for (int idx = tid; idx < CK * 9 * TCO; idx += 256) {
                int row = idx >> 7;        // ci_in*9 + tap
                int co_in = idx & 127;
                ws[idx] = wtp[(size_t)row * COUT + co_in];
            }
        }
        __syncthreads();

        #pragma unroll
        for (int kk = 0; kk < CK; ++kk) {
            const float* xp = xs + kk * 180 + r0 * 10 + c0;
            const float* wb = ws + kk * 9 * TCO + tx * 2;
            #pragma unroll
            for (int tap = 0; tap < 9; ++tap) {
                const int dr = tap / 3;
                const int dc = tap - dr * 3;
                unsigned long long xx[8];
                #pragma unroll
                for (int i = 0; i < 8; ++i) {
                    float v = xp[i * 20 + dr * 10 + dc];
                    xx[i] = pack2(v, v);
                }
                unsigned long long wv[4];
                #pragma unroll
                for (int jp = 0; jp < 4; ++jp)
                    wv[jp] = *reinterpret_cast<const unsigned long long*>(
                        wb + tap * TCO + jp * 32);
                #pragma unroll
                for (int i = 0; i < 8; ++i)
                    #pragma unroll
                    for (int jp = 0; jp < 4; ++jp)
                        fma2(acc2[i][jp], xx[i], wv[jp]);
            }
        }
    }

    // ---- epilogue: demodulate and store
    #pragma unroll
    for (int jp = 0; jp < 4; ++jp) {
        int co = co0 + jp * 32 + tx * 2;
        float g0 = g_g[(size_t)b * COUT + co];
        float g1 = g_g[(size_t)b * COUT + co + 1];
        #pragma unroll
        for (int i = 0; i < 8; ++i) {
            float lo, hi;
            unpack2(acc2[i][jp], lo, hi);
            int h = gr0 + r0 + 2 * i;
            int w = gc0 + c0;
            size_t base = (((size_t)b * COUT + co) * HDIM + h) * WDIM + w;
            out[base] = lo * g0;
            out[base + (size_t)HDIM * WDIM] = hi * g1;
        }
    }
}

extern "C" void kernel_launch(void* const* d_in, const int* in_sizes, int n_in,
                              void* d_out, int out_size) {
    const float* x          = (const float*)d_in[0];
    const float* style      = (const float*)d_in[1];
    const float* weight     = (const float*)d_in[2];
    const float* mod_weight = (const float*)d_in[3];
    const float* mod_bias   = (const float*)d_in[4];
    float* out = (float*)d_out;

    const long long conv_elems = (long long)BSZ * COUT * HDIM * WDIM;  // 16,777,216
    float* tail = (out_size >= conv_elems + BSZ * CIN) ? (out + conv_elems) : nullptr;

    k_style<<<(BSZ * CIN * 32) / 256, 256>>>(style, mod_weight, mod_bias, tail);
    k_wprep<<<(COUT * CIN) / 256, 256>>>(weight);
    k_demod<<<(BSZ * COUT * 32) / 256, 256>>>();

    dim3 grid((HDIM / TH) * (WDIM / TW), COUT / TCO, BSZ);  // (32, 4, 8)
    k_conv<<<grid, 256>>>(x, out);
}

// round 7
// speedup vs baseline: 1.6599x; 1.2466x over previous
#include <cuda_runtime.h>
#include <cuda_bf16.h>

// Shapes (fixed by the problem)
#define BSZ  8
#define CIN  512
#define COUT 512
#define SSZ  512
#define HDIM 64
#define WDIM 64

// conv tile config
#define TCO 128   // cout per block
#define TH  16    // spatial rows per block
#define TW  8     // spatial cols per block
#define CK  4     // cin chunk (double-buffered)

// padded x layout: rows 66 (=-1..64), row stride 72 floats (16B-aligned rows)
#define XPR 66
#define XPS 72
#define XPLANE (XPR * XPS)   // 4752

// Scratch (device globals: allocation-free)
__device__ float g_s[BSZ * CIN];                 // modulation s[b,ci]
__device__ float g_g[BSZ * COUT];                // epilogue scale conv_scale*demod
__device__ float g_wsq[COUT * CIN];              // sum_k weight^2
__device__ float g_wt[CIN * 9 * COUT];           // weight transposed [ci][tap][co]
__device__ float g_xs[(size_t)BSZ * CIN * XPLANE]; // padded, pre-modulated x

static __device__ __forceinline__ float warp_sum(float v) {
    #pragma unroll
    for (int o = 16; o; o >>= 1) v += __shfl_xor_sync(0xffffffffu, v, o);
    return v;
}

// ---- packed fp32x2 helpers (sm_103a FFMA2 path; ptxas never auto-fuses) ----
static __device__ __forceinline__ unsigned long long pack2(float lo, float hi) {
    unsigned long long r;
    asm("mov.b64 %0, {%1, %2};" : "=l"(r) : "f"(lo), "f"(hi));
    return r;
}
static __device__ __forceinline__ void fma2(unsigned long long& d,
                                            unsigned long long a,
                                            unsigned long long b) {
    asm("fma.rn.f32x2 %0, %1, %2, %0;" : "+l"(d) : "l"(a), "l"(b));
}
static __device__ __forceinline__ void unpack2(unsigned long long v, float& lo, float& hi) {
    asm("mov.b64 {%0, %1}, %2;" : "=f"(lo), "=f"(hi) : "l"(v));
}

// ---- cp.async helpers ----
static __device__ __forceinline__ unsigned smem_u32(const void* p) {
    return (unsigned)__cvta_generic_to_shared(p);
}
static __device__ __forceinline__ void cp16(unsigned dst, const void* src) {
    asm volatile("cp.async.cg.shared.global [%0], [%1], 16;" :: "r"(dst), "l"(src));
}
static __device__ __forceinline__ void cp_commit() {
    asm volatile("cp.async.commit_group;");
}
static __device__ __forceinline__ void cp_wait0() {
    asm volatile("cp.async.wait_group 0;");
}

// s[b,ci] = sum_t style[b,t] * mod_weight[ci,t] * lin_scale + mod_bias[ci]
__global__ void k_style(const float* __restrict__ style,
                        const float* __restrict__ mod_weight,
                        const float* __restrict__ mod_bias,
                        float* __restrict__ out_tail) {
    int warp = (blockIdx.x * blockDim.x + threadIdx.x) >> 5;
    int lane = threadIdx.x & 31;
    if (warp >= BSZ * CIN) return;
    int b = warp >> 9, ci = warp & 511;
    const float* st = style + (size_t)b * SSZ;
    const float* mw = mod_weight + (size_t)ci * SSZ;
    float acc = 0.f;
    for (int t = lane; t < SSZ; t += 32) acc += st[t] * mw[t];
    acc = warp_sum(acc);
    if (lane == 0) {
        const float lin_scale = 0.044194173824159216f;  // 1/sqrt(512)
        float v = acc * lin_scale + mod_bias[ci];
        g_s[warp] = v;
        if (out_tail) out_tail[warp] = v;   // s5 flattened = s[b,ci]
    }
}

// Transpose weight to [ci][tap][co] and compute Wsq[co,ci] = sum_k w^2
__global__ void k_wprep(const float* __restrict__ weight) {
    int idx = blockIdx.x * blockDim.x + threadIdx.x;
    if (idx >= COUT * CIN) return;
    int co = idx >> 9, ci = idx & 511;
    const float* wp = weight + (size_t)idx * 9;
    float sq = 0.f;
    #pragma unroll
    for (int k = 0; k < 9; ++k) {
        float v = wp[k];
        sq += v * v;
        g_wt[(size_t)(ci * 9 + k) * COUT + co] = v;
    }
    g_wsq[(size_t)co * CIN + ci] = sq;
}

// g[b,co] = conv_scale * rsqrt(conv_scale^2 * sum_ci s^2 * Wsq + eps)
__global__ void k_demod() {
    int warp = (blockIdx.x * blockDim.x + threadIdx.x) >> 5;
    int lane = threadIdx.x & 31;
    if (warp >= BSZ * COUT) return;
    int b = warp >> 9, co = warp & 511;
    const float* sp = g_s + (size_t)b * CIN;
    const float* wq = g_wsq + (size_t)co * CIN;
    float acc = 0.f;
    for (int t = lane; t < CIN; t += 32) {
        float sv = sp[t];
        acc += sv * sv * wq[t];
    }
    acc = warp_sum(acc);
    if (lane == 0) {
        const float cs = 0.014731391274719742f;  // 1/sqrt(512*9)
        g_g[warp] = cs * rsqrtf(cs * cs * acc + 1e-8f);
    }
}

// Pre-modulated, zero-padded x: g_xs[b][ci][pr][pc] = x[b][ci][pr-1][pc-1]*s[b,ci]
__global__ void k_xprep(const float* __restrict__ x) {
    int plane = blockIdx.x;             // b*512 + ci
    int b = plane >> 9;
    float s = g_s[plane];
    const float* xp = x + (size_t)plane * (HDIM * WDIM);
    float* dp = g_xs + (size_t)plane * XPLANE;
    for (int idx = threadIdx.x; idx < XPLANE; idx += blockDim.x) {
        int pr = idx / XPS;
        int pc = idx - pr * XPS;
        int gh = pr - 1, gw = pc - 1;
        float v = 0.f;
        if ((unsigned)gh < (unsigned)HDIM && (unsigned)gw < (unsigned)WDIM)
            v = xp[gh * WDIM + gw] * s;
        dp[idx] = v;
    }
    (void)b;
}

// Direct conv, packed fp32x2 FMA, cp.async double-buffered smem pipeline.
// Block = (b, co-tile 128, 16x8 spatial tile), 256 threads.
// Thread micro-tile: 8 spatial rows x 8 couts (4 adjacent f32x2 pairs).
__global__ __launch_bounds__(256, 2)
void k_conv(float* __restrict__ out) {
    __shared__ __align__(16) float xs[2][CK * 18 * 12];   // [ci_in][row 0..17][col 0..11]
    __shared__ __align__(16) float ws[2][CK * 9 * TCO];   // [ci_in][tap][co]

    const int tid = threadIdx.x;
    const int tx = tid & 15;       // -> cout pair base: co0 + jp*32 + tx*2
    const int ty = tid >> 4;       // -> spatial
    const int b   = blockIdx.z;
    const int co0 = blockIdx.y * TCO;
    const int gr0 = (blockIdx.x >> 3) * TH;   // 4 row tiles
    const int gc0 = (blockIdx.x & 7) * TW;    // 8 col tiles
    const int r0 = ty >> 3;        // 0..1
    const int c0 = ty & 7;         // 0..7

    unsigned long long acc2[8][4];
    #pragma unroll
    for (int i = 0; i < 8; ++i)
        #pragma unroll
        for (int jp = 0; jp < 4; ++jp) acc2[i][jp] = 0ull;

    const float* xbase = g_xs + ((size_t)b * CIN) * XPLANE + gr0 * XPS + gc0;
    const float* wbase = g_wt + co0;

    // ---- per-thread cp.async work assignment ----
    // xs: CK*18 rows x 3 float4 = CK*54 items (216 for CK=4)
    // ws: CK*9*128/4 = CK*288 items (1152)  -> 4.5 per thread
    const int xit = tid;                    // one xs item for tid<216
    int x_cin = 0, x_r = 0, x_q = 0;
    if (xit < CK * 54) {
        x_cin = xit / 54;
        int rem = xit - x_cin * 54;
        x_r = rem / 3;
        x_q = rem - x_r * 3;
    }

    // prologue: issue chunk 0
    {
        if (xit < CK * 54)
            cp16(smem_u32(&xs[0][(x_cin * 18 + x_r) * 12 + x_q * 4]),
                 xbase + (size_t)x_cin * XPLANE + x_r * XPS + x_q * 4);
        #pragma unroll
        for (int t = 0; t < 5; ++t) {
            int idx = tid + t * 256;
            if (idx < CK * 288) {
                int row = idx >> 5;          // ci_in*9 + tap
                int c4  = idx & 31;
                cp16(smem_u32(&ws[0][row * TCO + c4 * 4]),
                     wbase + (size_t)row * COUT + c4 * 4);
            }
        }
        cp_commit();
    }

    const int NCH = CIN / CK;   // 128
    for (int ch = 0; ch < NCH; ++ch) {
        const int cur = ch & 1;
        cp_wait0();
        __syncthreads();   // chunk ch ready; all warps past compute(ch-1)

        // issue chunk ch+1 into the other buffer (overlaps with compute below)
        if (ch + 1 < NCH) {
            const int nxt = cur ^ 1;
            const int ci0 = (ch + 1) * CK;
            if (xit < CK * 54)
                cp16(smem_u32(&xs[nxt][(x_cin * 18 + x_r) * 12 + x_q * 4]),
                     xbase + (size_t)(ci0 + x_cin) * XPLANE + x_r * XPS + x_q * 4);
            #pragma unroll
            for (int t = 0; t < 5; ++t) {
                int idx = tid + t * 256;
                if (idx < CK * 288) {
                    int row = idx >> 5;
                    int c4  = idx & 31;
                    cp16(smem_u32(&ws[nxt][row * TCO + c4 * 4]),
                         wbase + ((size_t)ci0 * 9 + row) * COUT + c4 * 4);
                }
            }
            cp_commit();
        } else {
            cp_commit();   // keep group count consistent for wait_group 0
        }

        // ---- compute chunk ch
        #pragma unroll
        for (int kk = 0; kk < CK; ++kk) {
            const float* xp = &xs[cur][kk * 216 + r0 * 12 + c0];
            const float* wb = &ws[cur][kk * 9 * TCO + tx * 2];
            #pragma unroll
            for (int tap = 0; tap < 9; ++tap) {
                const int dr = tap / 3;
                const int dc = tap - dr * 3;
                unsigned long long xx[8];
                #pragma unroll
                for (int i = 0; i < 8; ++i) {
                    float v = xp[i * 24 + dr * 12 + dc];
                    xx[i] = pack2(v, v);
                }
                unsigned long long wv[4];
                #pragma unroll
                for (int jp = 0; jp < 4; ++jp)
                    wv[jp] = *reinterpret_cast<const unsigned long long*>(
                        wb + tap * TCO + jp * 32);
                #pragma unroll
                for (int i = 0; i < 8; ++i)
                    #pragma unroll
                    for (int jp = 0; jp < 4; ++jp)
                        fma2(acc2[i][jp], xx[i], wv[jp]);
            }
        }
    }

    // ---- epilogue: demodulate and store
    #pragma unroll
    for (int jp = 0; jp < 4; ++jp) {
        int co = co0 + jp * 32 + tx * 2;
        float g0 = g_g[(size_t)b * COUT + co];
        float g1 = g_g[(size_t)b * COUT + co + 1];
        #pragma unroll
        for (int i = 0; i < 8; ++i) {
            float lo, hi;
            unpack2(acc2[i][jp], lo, hi);
            int h = gr0 + r0 + 2 * i;
            int w = gc0 + c0;
            size_t base = (((size_t)b * COUT + co) * HDIM + h) * WDIM + w;
            out[base] = lo * g0;
            out[base + (size_t)HDIM * WDIM] = hi * g1;
        }
    }
}

extern "C" void kernel_launch(void* const* d_in, const int* in_sizes, int n_in,
                              void* d_out, int out_size) {
    const float* x          = (const float*)d_in[0];
    const float* style      = (const float*)d_in[1];
    const float* weight     = (const float*)d_in[2];
    const float* mod_weight = (const float*)d_in[3];
    const float* mod_bias   = (const float*)d_in[4];
    float* out = (float*)d_out;

    const long long conv_elems = (long long)BSZ * COUT * HDIM * WDIM;  // 16,777,216
    float* tail = (out_size >= conv_elems + BSZ * CIN) ? (out + conv_elems) : nullptr;

    k_style<<<(BSZ * CIN * 32) / 256, 256>>>(style, mod_weight, mod_bias, tail);
    k_wprep<<<(COUT * CIN) / 256, 256>>>(weight);
    k_demod<<<(BSZ * COUT * 32) / 256, 256>>>();
    k_xprep<<<BSZ * CIN, 256>>>(x);

    dim3 grid((HDIM / TH) * (WDIM / TW), COUT / TCO, BSZ);  // (32, 4, 8)
    k_conv<<<grid, 256>>>(out);
}

// round 10
// speedup vs baseline: 2.7299x; 1.6446x over previous
#include <cuda_runtime.h>
#include <cuda_bf16.h>
#include <cstdint>

// Shapes (fixed)
#define BSZ  8
#define CIN  512
#define COUT 512
#define SSZ  512
#define HDIM 64
#define WDIM 64

// padded x: [b][pr 0..65][pc 0..65][ci], ci contiguous
#define XH 66
#define XW 66

// GEMM tiling
#define MT 128          // spatial tile 16x8
#define NT 128          // couts per block
#define KC 64           // ci per k-iter (64 bf16 = 128B row)
#define NITER 216       // 3 terms * 9 taps * 8 ci-chunks

// smem: 3 stages * (A 16KB + B 16KB) = 96KB; epilogue D[128n][132m] f32 = 67.6KB reuses it
#define NSTG 3
#define STGB 32768
#define SMEM_BYTES (NSTG * STGB + 1024)

// ---- device scratch (allocation-free) ----
__device__ float g_s[BSZ * CIN];
__device__ float g_g[BSZ * COUT];
__device__ float g_wsq[COUT * CIN];
__device__ __nv_bfloat16 g_xhi[(size_t)BSZ * XH * XW * CIN];
__device__ __nv_bfloat16 g_xlo[(size_t)BSZ * XH * XW * CIN];
__device__ __nv_bfloat16 g_whi[9 * COUT * CIN];   // [tap][co][ci]
__device__ __nv_bfloat16 g_wlo[9 * COUT * CIN];

static __device__ __forceinline__ float warp_sum(float v) {
    #pragma unroll
    for (int o = 16; o; o >>= 1) v += __shfl_xor_sync(0xffffffffu, v, o);
    return v;
}

// ---- PTX helpers (arch-generic only; no 'a'-gated features) ----
static __device__ __forceinline__ unsigned smem_u32(const void* p) {
    return (unsigned)__cvta_generic_to_shared(p);
}
static __device__ __forceinline__ void cp16(unsigned dst, const void* src) {
    asm volatile("cp.async.cg.shared.global [%0], [%1], 16;" :: "r"(dst), "l"(src));
}
static __device__ __forceinline__ void cp_commit() {
    asm volatile("cp.async.commit_group;");
}
static __device__ __forceinline__ void cp_wait1() {
    asm volatile("cp.async.wait_group 1;");
}
static __device__ __forceinline__ void ldm_x4(unsigned& r0, unsigned& r1,
                                              unsigned& r2, unsigned& r3, unsigned a) {
    asm volatile("ldmatrix.sync.aligned.m8n8.x4.shared.b16 {%0,%1,%2,%3}, [%4];"
                 : "=r"(r0), "=r"(r1), "=r"(r2), "=r"(r3) : "r"(a));
}
static __device__ __forceinline__ void mma16816(float* c, const unsigned* a, const unsigned* b) {
    asm volatile(
        "mma.sync.aligned.m16n8k16.row.col.f32.bf16.bf16.f32 "
        "{%0,%1,%2,%3}, {%4,%5,%6,%7}, {%8,%9}, {%0,%1,%2,%3};"
        : "+f"(c[0]), "+f"(c[1]), "+f"(c[2]), "+f"(c[3])
        : "r"(a[0]), "r"(a[1]), "r"(a[2]), "r"(a[3]), "r"(b[0]), "r"(b[1]));
}

#define SWZ(o) ((o) ^ (((o) >> 3) & 0x70))

// ================= prep kernels =================

__global__ void k_style(const float* __restrict__ style,
                        const float* __restrict__ mod_weight,
                        const float* __restrict__ mod_bias,
                        float* __restrict__ out_tail) {
    int warp = (blockIdx.x * blockDim.x + threadIdx.x) >> 5;
    int lane = threadIdx.x & 31;
    if (warp >= BSZ * CIN) return;
    int b = warp >> 9, ci = warp & 511;
    const float* st = style + (size_t)b * SSZ;
    const float* mw = mod_weight + (size_t)ci * SSZ;
    float acc = 0.f;
    for (int t = lane; t < SSZ; t += 32) acc += st[t] * mw[t];
    acc = warp_sum(acc);
    if (lane == 0) {
        const float lin_scale = 0.044194173824159216f;  // 1/sqrt(512)
        float v = acc * lin_scale + mod_bias[ci];
        g_s[warp] = v;
        if (out_tail) out_tail[warp] = v;
    }
}

__global__ void k_wprep(const float* __restrict__ weight) {
    int idx = blockIdx.x * blockDim.x + threadIdx.x;
    if (idx >= COUT * CIN) return;
    int co = idx >> 9, ci = idx & 511;
    const float* wp = weight + (size_t)idx * 9;
    float sq = 0.f;
    #pragma unroll
    for (int k = 0; k < 9; ++k) {
        float v = wp[k];
        sq += v * v;
        __nv_bfloat16 hi = __float2bfloat16_rn(v);
        __nv_bfloat16 lo = __float2bfloat16_rn(v - __bfloat162float(hi));
        size_t dst = (size_t)k * (COUT * CIN) + (size_t)co * CIN + ci;
        g_whi[dst] = hi;
        g_wlo[dst] = lo;
    }
    g_wsq[(size_t)co * CIN + ci] = sq;
}

__global__ void k_demod() {
    int warp = (blockIdx.x * blockDim.x + threadIdx.x) >> 5;
    int lane = threadIdx.x & 31;
    if (warp >= BSZ * COUT) return;
    int b = warp >> 9, co = warp & 511;
    const float* sp = g_s + (size_t)b * CIN;
    const float* wq = g_wsq + (size_t)co * CIN;
    float acc = 0.f;
    for (int t = lane; t < CIN; t += 32) {
        float sv = sp[t];
        acc += sv * sv * wq[t];
    }
    acc = warp_sum(acc);
    if (lane == 0) {
        const float cs = 0.014731391274719742f;  // 1/sqrt(512*9)
        g_g[warp] = cs * rsqrtf(cs * cs * acc + 1e-8f);
    }
}

__global__ void k_xhalo() {
    int gid = blockIdx.x * blockDim.x + threadIdx.x;
    const int total = BSZ * 260 * CIN;
    if (gid >= total) return;
    int ci = gid & 511;
    int r = gid >> 9;
    int bp = r % 260;
    int b = r / 260;
    int pr, pc;
    if (bp < 66)       { pr = 0;        pc = bp; }
    else if (bp < 132) { pr = 65;       pc = bp - 66; }
    else if (bp < 196) { pr = bp - 131; pc = 0; }
    else               { pr = bp - 195; pc = 65; }
    size_t dst = (((size_t)b * XH + pr) * XW + pc) * CIN + ci;
    g_xhi[dst] = __float2bfloat16_rn(0.f);
    g_xlo[dst] = __float2bfloat16_rn(0.f);
}

__global__ void k_xprep(const float* __restrict__ x) {
    __shared__ float sx[128][65];
    int b = blockIdx.x >> 6;
    int h = blockIdx.x & 63;
    int tid = threadIdx.x;
    for (int cb = 0; cb < 4; ++cb) {
        int cbase = cb * 128;
        __syncthreads();
        {
            int w = tid & 63;
            int cl = tid >> 6;
            for (int k = 0; k < 32; ++k) {
                int ci = cl + k * 4;
                sx[ci][w] = x[(((size_t)b * CIN + cbase + ci) * HDIM + h) * WDIM + w];
            }
        }
        __syncthreads();
        for (int k = 0; k < 32; ++k) {
            int idx = tid + k * 256;
            int w = idx >> 7;
            int ci = idx & 127;
            float s = g_s[b * CIN + cbase + ci];
            float v = sx[ci][w] * s;
            __nv_bfloat16 hi = __float2bfloat16_rn(v);
            __nv_bfloat16 lo = __float2bfloat16_rn(v - __bfloat162float(hi));
            size_t dst = (((size_t)b * XH + h + 1) * XW + (w + 1)) * CIN + cbase + ci;
            g_xhi[dst] = hi;
            g_xlo[dst] = lo;
        }
    }
}

// ================= main conv: mma.sync bf16 implicit GEMM =================
__global__ __launch_bounds__(256, 2)
void k_conv(float* __restrict__ out) {
    extern __shared__ char dyn_smem[];
    const unsigned sbase = (smem_u32(dyn_smem) + 1023u) & ~1023u;

    const int tid = threadIdx.x;
    const int wid = tid >> 5;
    const int lane = tid & 31;
    const int warp_m = wid & 3;       // m32 slice
    const int warp_n = wid >> 2;      // n64 slice
    const int b   = blockIdx.z;
    const int co0 = blockIdx.y * NT;
    const int gr0 = (int)(blockIdx.x >> 3) * 16;
    const int gc0 = (int)(blockIdx.x & 7) * 8;

    float acc[2][8][4];
    #pragma unroll
    for (int mt = 0; mt < 2; ++mt)
        #pragma unroll
        for (int nt = 0; nt < 8; ++nt)
            #pragma unroll
            for (int r = 0; r < 4; ++r) acc[mt][nt][r] = 0.f;

    // ---- cp.async per-thread constants: A 1024 chunks, B 1024 chunks; 4 each ----
    unsigned dstAo[4], dstBo[4];   // stage-relative swizzled offsets
    unsigned srcA[4], srcB[4];
    #pragma unroll
    for (int t = 0; t < 4; ++t) {
        int idx = tid + t * 256;               // 0..1023
        unsigned so = SWZ((unsigned)idx * 16u);
        dstAo[t] = so;
        dstBo[t] = so;
        int m = idx >> 3, q = idx & 7;
        srcA[t] = (unsigned)(((gr0 + (m >> 3)) * XW + gc0 + (m & 7)) * (CIN * 2)) + q * 16;
        srcB[t] = (unsigned)(m * (CIN * 2)) + q * 16;   // m here = n row for B
    }
    const size_t bxoff = (size_t)b * XH * XW * (CIN * 2);

    auto iter_bases = [&](int s, const char*& uA, const char*& uB) {
        int term = s / 72;
        int r2 = s - term * 72;
        int tap = r2 >> 3;
        int kc = r2 & 7;
        int dr = tap / 3, dc = tap - dr * 3;
        const char* xp = (term == 1) ? (const char*)g_xlo : (const char*)g_xhi;
        const char* wp = (term == 2) ? (const char*)g_wlo : (const char*)g_whi;
        uA = xp + bxoff + (size_t)((dr * XW + dc) * (CIN * 2)) + kc * (KC * 2);
        uB = wp + (size_t)tap * (COUT * CIN * 2) + (size_t)co0 * (CIN * 2) + kc * (KC * 2);
    };

    auto issue_copies = [&](int stage, int s) {
        const char *uA, *uB;
        iter_bases(s, uA, uB);
        unsigned sa = sbase + stage * STGB;
        unsigned sb = sa + 16384;
        #pragma unroll
        for (int t = 0; t < 4; ++t) cp16(sa + dstAo[t], uA + srcA[t]);
        #pragma unroll
        for (int t = 0; t < 4; ++t) cp16(sb + dstBo[t], uB + srcB[t]);
        cp_commit();
    };

    // ---- ldmatrix per-thread address components ----
    // A: lanes 0-15 -> rows m0..m0+15 (k-chunk low), lanes 16-31 same rows k-chunk high
    const int a_row[2] = { warp_m * 32 + 0 * 16 + (lane & 15),
                           warp_m * 32 + 1 * 16 + (lane & 15) };
    const int a_csel = lane >> 4;                     // 0/1
    // B: row = n16 base + ((lane>>4)<<3) + (lane&7); chunk sel = (lane>>3)&1
    int b_row[4];
    #pragma unroll
    for (int q = 0; q < 4; ++q)
        b_row[q] = warp_n * 64 + q * 16 + (((lane >> 4) & 1) << 3) + (lane & 7);
    const int b_csel = (lane >> 3) & 1;

    // prologue: iters 0,1 into stages 0,1
    issue_copies(0, 0);
    issue_copies(1, 1);

    for (int s = 0; s < NITER; ++s) {
        const int st = s % NSTG;
        cp_wait1();
        __syncthreads();

        if (s + 2 < NITER) issue_copies((s + 2) % NSTG, s + 2);
        else cp_commit();

        const unsigned sa = sbase + st * STGB;
        const unsigned sb = sa + 16384;

        #pragma unroll
        for (int ks = 0; ks < 4; ++ks) {
            unsigned af[2][4];
            #pragma unroll
            for (int mt = 0; mt < 2; ++mt) {
                int row = a_row[mt];
                unsigned addr = sa + row * 128 + (((2 * ks + a_csel) ^ (row & 7)) << 4);
                ldm_x4(af[mt][0], af[mt][1], af[mt][2], af[mt][3], addr);
            }
            unsigned bf[8][2];
            #pragma unroll
            for (int q = 0; q < 4; ++q) {
                int row = b_row[q];
                unsigned addr = sb + row * 128 + (((2 * ks + b_csel) ^ (row & 7)) << 4);
                unsigned r0, r1, r2, r3;
                ldm_x4(r0, r1, r2, r3, addr);
                bf[2 * q][0] = r0;  bf[2 * q][1] = r1;
                bf[2 * q + 1][0] = r2;  bf[2 * q + 1][1] = r3;
            }
            #pragma unroll
            for (int mt = 0; mt < 2; ++mt)
                #pragma unroll
                for (int nt = 0; nt < 8; ++nt)
                    mma16816(acc[mt][nt], af[mt], bf[nt]);
        }
    }

    // ================= epilogue: smem transpose -> coalesced demod store =====
    __syncthreads();
    float* smemD = (float*)(dyn_smem + ((1024 - (smem_u32(dyn_smem) & 1023)) & 1023));
    // store acc as D[n][m], row stride 132 (conflict-free both directions)
    #pragma unroll
    for (int mt = 0; mt < 2; ++mt)
        #pragma unroll
        for (int nt = 0; nt < 8; ++nt) {
            int n = warp_n * 64 + nt * 8 + (lane & 3) * 2;
            int m = warp_m * 32 + mt * 16 + (lane >> 2);
            smemD[n * 132 + m]             = acc[mt][nt][0];
            smemD[(n + 1) * 132 + m]       = acc[mt][nt][1];
            smemD[n * 132 + m + 8]         = acc[mt][nt][2];
            smemD[(n + 1) * 132 + m + 8]   = acc[mt][nt][3];
        }
    __syncthreads();

    #pragma unroll 4
    for (int it = 0; it < 64; ++it) {
        int idx = tid + it * 256;       // 0..16383
        int n = idx >> 7;
        int m = idx & 127;
        int co = co0 + n;
        int h = gr0 + (m >> 3);
        int w = gc0 + (m & 7);
        float gm = g_g[b * COUT + co];
        out[(((size_t)b * COUT + co) * HDIM + h) * WDIM + w] = smemD[n * 132 + m] * gm;
    }
}

extern "C" void kernel_launch(void* const* d_in, const int* in_sizes, int n_in,
                              void* d_out, int out_size) {
    const float* x          = (const float*)d_in[0];
    const float* style      = (const float*)d_in[1];
    const float* weight     = (const float*)d_in[2];
    const float* mod_weight = (const float*)d_in[3];
    const float* mod_bias   = (const float*)d_in[4];
    float* out = (float*)d_out;

    const long long conv_elems = (long long)BSZ * COUT * HDIM * WDIM;
    float* tail = (out_size >= conv_elems + BSZ * CIN) ? (out + conv_elems) : nullptr;

    cudaFuncSetAttribute(k_conv, cudaFuncAttributeMaxDynamicSharedMemorySize, SMEM_BYTES);

    k_style<<<(BSZ * CIN * 32) / 256, 256>>>(style, mod_weight, mod_bias, tail);
    k_wprep<<<(COUT * CIN) / 256, 256>>>(weight);
    k_demod<<<(BSZ * COUT * 32) / 256, 256>>>();
    k_xhalo<<<(BSZ * 260 * CIN + 255) / 256, 256>>>();
    k_xprep<<<BSZ * HDIM, 256>>>(x);

    dim3 grid(32, COUT / NT, BSZ);   // (32, 4, 8)
    k_conv<<<grid, 256, SMEM_BYTES>>>(out);
}

// round 11
// speedup vs baseline: 10.7593x; 3.9413x over previous
#include <cuda_runtime.h>
#include <cuda_fp16.h>
#include <cuda_bf16.h>
#include <cstdint>

// Shapes (fixed)
#define BSZ  8
#define CIN  512
#define COUT 512
#define SSZ  512
#define HDIM 64
#define WDIM 64

// padded x: [b][pr 0..65][pc 0..65][ci], ci contiguous
#define XH 66
#define XW 66

// GEMM tiling
#define MT 128          // spatial tile 16x8
#define NT 128          // couts per block
#define KC 64           // ci per k-iter (64 fp16 = 128B row)
#define NITER 72        // 9 taps * 8 ci-chunks (single fp16 term)

// smem: 3 stages * (A 16KB + B 16KB) = 96KB; epilogue D[128n][132m] f32 reuses it
#define NSTG 3
#define STGB 32768
#define SMEM_BYTES (NSTG * STGB + 1024)

// ---- device scratch (allocation-free) ----
__device__ float g_s[BSZ * CIN];
__device__ float g_g[BSZ * COUT];
__device__ float g_wsq[COUT * CIN];
__device__ __half g_xh[(size_t)BSZ * XH * XW * CIN];   // modulated x, fp16
__device__ __half g_w[9 * COUT * CIN];                 // [tap][co][ci], fp16

static __device__ __forceinline__ float warp_sum(float v) {
    #pragma unroll
    for (int o = 16; o; o >>= 1) v += __shfl_xor_sync(0xffffffffu, v, o);
    return v;
}

// ---- PTX helpers (arch-generic only) ----
static __device__ __forceinline__ unsigned smem_u32(const void* p) {
    return (unsigned)__cvta_generic_to_shared(p);
}
static __device__ __forceinline__ void cp16(unsigned dst, const void* src) {
    asm volatile("cp.async.cg.shared.global [%0], [%1], 16;" :: "r"(dst), "l"(src));
}
static __device__ __forceinline__ void cp_commit() {
    asm volatile("cp.async.commit_group;");
}
static __device__ __forceinline__ void cp_wait1() {
    asm volatile("cp.async.wait_group 1;");
}
static __device__ __forceinline__ void ldm_x4(unsigned& r0, unsigned& r1,
                                              unsigned& r2, unsigned& r3, unsigned a) {
    asm volatile("ldmatrix.sync.aligned.m8n8.x4.shared.b16 {%0,%1,%2,%3}, [%4];"
                 : "=r"(r0), "=r"(r1), "=r"(r2), "=r"(r3) : "r"(a));
}
static __device__ __forceinline__ void mma16816(float* c, const unsigned* a, const unsigned* b) {
    asm volatile(
        "mma.sync.aligned.m16n8k16.row.col.f32.f16.f16.f32 "
        "{%0,%1,%2,%3}, {%4,%5,%6,%7}, {%8,%9}, {%0,%1,%2,%3};"
        : "+f"(c[0]), "+f"(c[1]), "+f"(c[2]), "+f"(c[3])
        : "r"(a[0]), "r"(a[1]), "r"(a[2]), "r"(a[3]), "r"(b[0]), "r"(b[1]));
}

#define SWZ(o) ((o) ^ (((o) >> 3) & 0x70))

// ================= prep kernels =================

__global__ void k_style(const float* __restrict__ style,
                        const float* __restrict__ mod_weight,
                        const float* __restrict__ mod_bias,
                        float* __restrict__ out_tail) {
    int warp = (blockIdx.x * blockDim.x + threadIdx.x) >> 5;
    int lane = threadIdx.x & 31;
    if (warp >= BSZ * CIN) return;
    int b = warp >> 9, ci = warp & 511;
    const float* st = style + (size_t)b * SSZ;
    const float* mw = mod_weight + (size_t)ci * SSZ;
    float acc = 0.f;
    for (int t = lane; t < SSZ; t += 32) acc += st[t] * mw[t];
    acc = warp_sum(acc);
    if (lane == 0) {
        const float lin_scale = 0.044194173824159216f;  // 1/sqrt(512)
        float v = acc * lin_scale + mod_bias[ci];
        g_s[warp] = v;
        if (out_tail) out_tail[warp] = v;
    }
}

__global__ void k_wprep(const float* __restrict__ weight) {
    int idx = blockIdx.x * blockDim.x + threadIdx.x;
    if (idx >= COUT * CIN) return;
    int co = idx >> 9, ci = idx & 511;
    const float* wp = weight + (size_t)idx * 9;
    float sq = 0.f;
    #pragma unroll
    for (int k = 0; k < 9; ++k) {
        float v = wp[k];
        sq += v * v;
        g_w[(size_t)k * (COUT * CIN) + (size_t)co * CIN + ci] = __float2half_rn(v);
    }
    g_wsq[(size_t)co * CIN + ci] = sq;
}

__global__ void k_demod() {
    int warp = (blockIdx.x * blockDim.x + threadIdx.x) >> 5;
    int lane = threadIdx.x & 31;
    if (warp >= BSZ * COUT) return;
    int b = warp >> 9, co = warp & 511;
    const float* sp = g_s + (size_t)b * CIN;
    const float* wq = g_wsq + (size_t)co * CIN;
    float acc = 0.f;
    for (int t = lane; t < CIN; t += 32) {
        float sv = sp[t];
        acc += sv * sv * wq[t];
    }
    acc = warp_sum(acc);
    if (lane == 0) {
        const float cs = 0.014731391274719742f;  // 1/sqrt(512*9)
        g_g[warp] = cs * rsqrtf(cs * cs * acc + 1e-8f);
    }
}

__global__ void k_xhalo() {
    int gid = blockIdx.x * blockDim.x + threadIdx.x;
    const int total = BSZ * 260 * CIN;
    if (gid >= total) return;
    int ci = gid & 511;
    int r = gid >> 9;
    int bp = r % 260;
    int b = r / 260;
    int pr, pc;
    if (bp < 66)       { pr = 0;        pc = bp; }
    else if (bp < 132) { pr = 65;       pc = bp - 66; }
    else if (bp < 196) { pr = bp - 131; pc = 0; }
    else               { pr = bp - 195; pc = 65; }
    g_xh[(((size_t)b * XH + pr) * XW + pc) * CIN + ci] = __float2half_rn(0.f);
}

__global__ void k_xprep(const float* __restrict__ x) {
    __shared__ float sx[128][65];
    int b = blockIdx.x >> 6;
    int h = blockIdx.x & 63;
    int tid = threadIdx.x;
    for (int cb = 0; cb < 4; ++cb) {
        int cbase = cb * 128;
        __syncthreads();
        {
            int w = tid & 63;
            int cl = tid >> 6;
            for (int k = 0; k < 32; ++k) {
                int ci = cl + k * 4;
                sx[ci][w] = x[(((size_t)b * CIN + cbase + ci) * HDIM + h) * WDIM + w];
            }
        }
        __syncthreads();
        for (int k = 0; k < 32; ++k) {
            int idx = tid + k * 256;
            int w = idx >> 7;
            int ci = idx & 127;
            float s = g_s[b * CIN + cbase + ci];
            float v = sx[ci][w] * s;
            g_xh[(((size_t)b * XH + h + 1) * XW + (w + 1)) * CIN + cbase + ci] =
                __float2half_rn(v);
        }
    }
}

// ================= main conv: mma.sync fp16 implicit GEMM =================
__global__ __launch_bounds__(256, 2)
void k_conv(float* __restrict__ out) {
    extern __shared__ char dyn_smem[];
    const unsigned sbase = (smem_u32(dyn_smem) + 1023u) & ~1023u;

    const int tid = threadIdx.x;
    const int wid = tid >> 5;
    const int lane = tid & 31;
    const int warp_m = wid & 3;       // m32 slice
    const int warp_n = wid >> 2;      // n64 slice
    const int b   = blockIdx.z;
    const int co0 = blockIdx.y * NT;
    const int gr0 = (int)(blockIdx.x >> 3) * 16;
    const int gc0 = (int)(blockIdx.x & 7) * 8;

    float acc[2][8][4];
    #pragma unroll
    for (int mt = 0; mt < 2; ++mt)
        #pragma unroll
        for (int nt = 0; nt < 8; ++nt)
            #pragma unroll
            for (int r = 0; r < 4; ++r) acc[mt][nt][r] = 0.f;

    // ---- cp.async per-thread constants ----
    unsigned dstO[4];
    unsigned srcA[4], srcB[4];
    #pragma unroll
    for (int t = 0; t < 4; ++t) {
        int idx = tid + t * 256;               // 0..1023
        dstO[t] = SWZ((unsigned)idx * 16u);
        int m = idx >> 3, q = idx & 7;
        srcA[t] = (unsigned)(((gr0 + (m >> 3)) * XW + gc0 + (m & 7)) * (CIN * 2)) + q * 16;
        srcB[t] = (unsigned)(m * (CIN * 2)) + q * 16;   // m = n row for B
    }
    const size_t bxoff = (size_t)b * XH * XW * (CIN * 2);

    auto iter_bases = [&](int s, const char*& uA, const char*& uB) {
        int tap = s >> 3;
        int kc = s & 7;
        int dr = tap / 3, dc = tap - dr * 3;
        uA = (const char*)g_xh + bxoff + (size_t)((dr * XW + dc) * (CIN * 2)) + kc * (KC * 2);
        uB = (const char*)g_w + (size_t)tap * (COUT * CIN * 2)
             + (size_t)co0 * (CIN * 2) + kc * (KC * 2);
    };

    auto issue_copies = [&](int stage, int s) {
        const char *uA, *uB;
        iter_bases(s, uA, uB);
        unsigned sa = sbase + stage * STGB;
        unsigned sb = sa + 16384;
        #pragma unroll
        for (int t = 0; t < 4; ++t) cp16(sa + dstO[t], uA + srcA[t]);
        #pragma unroll
        for (int t = 0; t < 4; ++t) cp16(sb + dstO[t], uB + srcB[t]);
        cp_commit();
    };

    // ---- ldmatrix per-thread address components ----
    const int a_row[2] = { warp_m * 32 + 0 * 16 + (lane & 15),
                           warp_m * 32 + 1 * 16 + (lane & 15) };
    const int a_csel = lane >> 4;                     // 0/1
    int b_row[4];
    #pragma unroll
    for (int q = 0; q < 4; ++q)
        b_row[q] = warp_n * 64 + q * 16 + (((lane >> 4) & 1) << 3) + (lane & 7);
    const int b_csel = (lane >> 3) & 1;

    // prologue: iters 0,1 into stages 0,1
    issue_copies(0, 0);
    issue_copies(1, 1);

    for (int s = 0; s < NITER; ++s) {
        const int st = s % NSTG;
        cp_wait1();
        __syncthreads();

        if (s + 2 < NITER) issue_copies((s + 2) % NSTG, s + 2);
        else cp_commit();

        const unsigned sa = sbase + st * STGB;
        const unsigned sb = sa + 16384;

        #pragma unroll
        for (int ks = 0; ks < 4; ++ks) {
            unsigned af[2][4];
            #pragma unroll
            for (int mt = 0; mt < 2; ++mt) {
                int row = a_row[mt];
                unsigned addr = sa + row * 128 + (((2 * ks + a_csel) ^ (row & 7)) << 4);
                ldm_x4(af[mt][0], af[mt][1], af[mt][2], af[mt][3], addr);
            }
            unsigned bf[8][2];
            #pragma unroll
            for (int q = 0; q < 4; ++q) {
                int row = b_row[q];
                unsigned addr = sb + row * 128 + (((2 * ks + b_csel) ^ (row & 7)) << 4);
                unsigned r0, r1, r2, r3;
                ldm_x4(r0, r1, r2, r3, addr);
                bf[2 * q][0] = r0;  bf[2 * q][1] = r1;
                bf[2 * q + 1][0] = r2;  bf[2 * q + 1][1] = r3;
            }
            #pragma unroll
            for (int mt = 0; mt < 2; ++mt)
                #pragma unroll
                for (int nt = 0; nt < 8; ++nt)
                    mma16816(acc[mt][nt], af[mt], bf[nt]);
        }
    }

    // ================= epilogue: smem transpose -> coalesced demod store =====
    __syncthreads();
    float* smemD = (float*)(dyn_smem + ((1024 - (smem_u32(dyn_smem) & 1023)) & 1023));
    #pragma unroll
    for (int mt = 0; mt < 2; ++mt)
        #pragma unroll
        for (int nt = 0; nt < 8; ++nt) {
            int n = warp_n * 64 + nt * 8 + (lane & 3) * 2;
            int m = warp_m * 32 + mt * 16 + (lane >> 2);
            smemD[n * 132 + m]             = acc[mt][nt][0];
            smemD[(n + 1) * 132 + m]       = acc[mt][nt][1];
            smemD[n * 132 + m + 8]         = acc[mt][nt][2];
            smemD[(n + 1) * 132 + m + 8]   = acc[mt][nt][3];
        }
    __syncthreads();

    #pragma unroll 4
    for (int it = 0; it < 64; ++it) {
        int idx = tid + it * 256;       // 0..16383
        int n = idx >> 7;
        int m = idx & 127;
        int co = co0 + n;
        int h = gr0 + (m >> 3);
        int w = gc0 + (m & 7);
        float gm = g_g[b * COUT + co];
        out[(((size_t)b * COUT + co) * HDIM + h) * WDIM + w] = smemD[n * 132 + m] * gm;
    }
}

extern "C" void kernel_launch(void* const* d_in, const int* in_sizes, int n_in,
                              void* d_out, int out_size) {
    const float* x          = (const float*)d_in[0];
    const float* style      = (const float*)d_in[1];
    const float* weight     = (const float*)d_in[2];
    const float* mod_weight = (const float*)d_in[3];
    const float* mod_bias   = (const float*)d_in[4];
    float* out = (float*)d_out;

    const long long conv_elems = (long long)BSZ * COUT * HDIM * WDIM;
    float* tail = (out_size >= conv_elems + BSZ * CIN) ? (out + conv_elems) : nullptr;

    cudaFuncSetAttribute(k_conv, cudaFuncAttributeMaxDynamicSharedMemorySize, SMEM_BYTES);

    k_style<<<(BSZ * CIN * 32) / 256, 256>>>(style, mod_weight, mod_bias, tail);
    k_wprep<<<(COUT * CIN) / 256, 256>>>(weight);
    k_demod<<<(BSZ * COUT * 32) / 256, 256>>>();
    k_xhalo<<<(BSZ * 260 * CIN + 255) / 256, 256>>>();
    k_xprep<<<BSZ * HDIM, 256>>>(x);

    dim3 grid(32, COUT / NT, BSZ);   // (32, 4, 8)
    k_conv<<<grid, 256, SMEM_BYTES>>>(out);
}

// round 12
// speedup vs baseline: 11.2730x; 1.0477x over previous
#include <cuda_runtime.h>
#include <cuda_fp16.h>
#include <cuda_bf16.h>
#include <cstdint>

// Shapes (fixed)
#define BSZ  8
#define CIN  512
#define COUT 512
#define SSZ  512
#define HDIM 64
#define WDIM 64

// padded x: [b][pr 0..65][pc 0..65][ci], ci contiguous
#define XH 66
#define XW 66

// GEMM tiling
#define MT 128          // spatial tile 16x8
#define NT 128          // couts per block
#define KC 64           // ci per k-iter (64 fp16 = 128B row)
#define NITER 72        // 9 taps * 8 ci-chunks (single fp16 term)

// smem: 3 stages * (A 16KB + B 16KB) = 96KB; epilogue D[128n][132m] f32 + g[128] reuses it
#define NSTG 3
#define STGB 32768
#define SMEM_BYTES (NSTG * STGB + 1024)

// ---- device scratch (allocation-free) ----
__device__ float g_s[BSZ * CIN];
__device__ float g_g[BSZ * COUT];
__device__ float g_wsq[COUT * CIN];
__device__ __half g_xh[(size_t)BSZ * XH * XW * CIN];   // modulated x, fp16
__device__ __half g_w[9 * COUT * CIN];                 // [tap][co][ci], fp16

static __device__ __forceinline__ float warp_sum(float v) {
    #pragma unroll
    for (int o = 16; o; o >>= 1) v += __shfl_xor_sync(0xffffffffu, v, o);
    return v;
}

// ---- PTX helpers (arch-generic only) ----
static __device__ __forceinline__ unsigned smem_u32(const void* p) {
    return (unsigned)__cvta_generic_to_shared(p);
}
static __device__ __forceinline__ void cp16(unsigned dst, const void* src) {
    asm volatile("cp.async.cg.shared.global [%0], [%1], 16;" :: "r"(dst), "l"(src));
}
static __device__ __forceinline__ void cp_commit() {
    asm volatile("cp.async.commit_group;");
}
static __device__ __forceinline__ void cp_wait1() {
    asm volatile("cp.async.wait_group 1;");
}
static __device__ __forceinline__ void ldm_x4(unsigned& r0, unsigned& r1,
                                              unsigned& r2, unsigned& r3, unsigned a) {
    asm volatile("ldmatrix.sync.aligned.m8n8.x4.shared.b16 {%0,%1,%2,%3}, [%4];"
                 : "=r"(r0), "=r"(r1), "=r"(r2), "=r"(r3) : "r"(a));
}
static __device__ __forceinline__ void mma16816(float* c, const unsigned* a, const unsigned* b) {
    asm volatile(
        "mma.sync.aligned.m16n8k16.row.col.f32.f16.f16.f32 "
        "{%0,%1,%2,%3}, {%4,%5,%6,%7}, {%8,%9}, {%0,%1,%2,%3};"
        : "+f"(c[0]), "+f"(c[1]), "+f"(c[2]), "+f"(c[3])
        : "r"(a[0]), "r"(a[1]), "r"(a[2]), "r"(a[3]), "r"(b[0]), "r"(b[1]));
}

#define SWZ(o) ((o) ^ (((o) >> 3) & 0x70))

// ================= prep kernels =================

// fused: blocks [0,512) do style GEMV; blocks [512,1536) do weight fp16 conversion + wsq
__global__ void k_prep0(const float* __restrict__ style,
                        const float* __restrict__ mod_weight,
                        const float* __restrict__ mod_bias,
                        const float* __restrict__ weight,
                        float* __restrict__ out_tail) {
    int tid = threadIdx.x;
    if (blockIdx.x < 512) {
        int warp = (blockIdx.x * 256 + tid) >> 5;   // 0..4095 = b*512+ci
        int lane = tid & 31;
        int b = warp >> 9, ci = warp & 511;
        const float* st = style + (size_t)b * SSZ;
        const float* mw = mod_weight + (size_t)ci * SSZ;
        float acc = 0.f;
        for (int t = lane; t < SSZ; t += 32) acc += st[t] * mw[t];
        acc = warp_sum(acc);
        if (lane == 0) {
            const float lin_scale = 0.044194173824159216f;  // 1/sqrt(512)
            float v = acc * lin_scale + mod_bias[ci];
            g_s[warp] = v;
            if (out_tail) out_tail[warp] = v;
        }
    } else {
        int idx = (blockIdx.x - 512) * 256 + tid;   // 0..262143 = co*512+ci
        int co = idx >> 9, ci = idx & 511;
        const float* wp = weight + (size_t)idx * 9;
        float sq = 0.f;
        #pragma unroll
        for (int k = 0; k < 9; ++k) {
            float v = wp[k];
            sq += v * v;
            g_w[(size_t)k * (COUT * CIN) + (size_t)co * CIN + ci] = __float2half_rn(v);
        }
        g_wsq[(size_t)co * CIN + ci] = sq;
    }
}

__global__ void k_demod() {
    int warp = (blockIdx.x * blockDim.x + threadIdx.x) >> 5;
    int lane = threadIdx.x & 31;
    if (warp >= BSZ * COUT) return;
    int b = warp >> 9, co = warp & 511;
    const float* sp = g_s + (size_t)b * CIN;
    const float* wq = g_wsq + (size_t)co * CIN;
    float acc = 0.f;
    for (int t = lane; t < CIN; t += 32) {
        float sv = sp[t];
        acc += sv * sv * wq[t];
    }
    acc = warp_sum(acc);
    if (lane == 0) {
        const float cs = 0.014731391274719742f;  // 1/sqrt(512*9)
        g_g[warp] = cs * rsqrtf(cs * cs * acc + 1e-8f);
    }
}

// x -> padded, modulated fp16 (with fused halo zeroing). Block = (b, h row).
__global__ void k_xprep(const float* __restrict__ x) {
    __shared__ float sx[128][65];
    int b = blockIdx.x >> 6;
    int h = blockIdx.x & 63;
    int tid = threadIdx.x;

    // fused halo: this block owns padded row pr=h+1 -> zero its pc=0 and pc=65 cells.
    {
        // 2*512 halfs = 512 uint; 256 threads x 2
        unsigned* c0 = (unsigned*)(g_xh + (((size_t)b * XH + h + 1) * XW + 0) * CIN);
        unsigned* c1 = (unsigned*)(g_xh + (((size_t)b * XH + h + 1) * XW + 65) * CIN);
        c0[tid] = 0u;
        c1[tid] = 0u;
    }
    if (h == 0) {   // full top border row pr=0
        uint4* p = (uint4*)(g_xh + ((size_t)b * XH + 0) * XW * CIN);
        for (int i = tid; i < (XW * CIN) / 8; i += 256) p[i] = make_uint4(0, 0, 0, 0);
    }
    if (h == 63) {  // full bottom border row pr=65
        uint4* p = (uint4*)(g_xh + ((size_t)b * XH + 65) * XW * CIN);
        for (int i = tid; i < (XW * CIN) / 8; i += 256) p[i] = make_uint4(0, 0, 0, 0);
    }

    for (int cb = 0; cb < 4; ++cb) {
        int cbase = cb * 128;
        __syncthreads();
        {
            int w = tid & 63;
            int cl = tid >> 6;
            for (int k = 0; k < 32; ++k) {
                int ci = cl + k * 4;
                sx[ci][w] = x[(((size_t)b * CIN + cbase + ci) * HDIM + h) * WDIM + w];
            }
        }
        __syncthreads();
        // half2 stores: 64 w * 64 ci-pairs = 4096 items
        for (int k = 0; k < 16; ++k) {
            int idx = tid + k * 256;
            int w = idx >> 6;
            int cp = idx & 63;
            int ci = cp * 2;
            float s0 = g_s[b * CIN + cbase + ci];
            float s1 = g_s[b * CIN + cbase + ci + 1];
            __half2 hv = __floats2half2_rn(sx[ci][w] * s0, sx[ci + 1][w] * s1);
            *(__half2*)(g_xh + (((size_t)b * XH + h + 1) * XW + (w + 1)) * CIN
                        + cbase + ci) = hv;
        }
    }
}

// ================= main conv: mma.sync fp16 implicit GEMM =================
__global__ __launch_bounds__(256, 2)
void k_conv(float* __restrict__ out) {
    extern __shared__ char dyn_smem[];
    const unsigned sbase = (smem_u32(dyn_smem) + 1023u) & ~1023u;

    const int tid = threadIdx.x;
    const int wid = tid >> 5;
    const int lane = tid & 31;
    const int warp_m = wid & 3;       // m32 slice
    const int warp_n = wid >> 2;      // n64 slice
    const int b   = blockIdx.z;
    const int co0 = blockIdx.y * NT;
    const int gr0 = (int)(blockIdx.x >> 3) * 16;
    const int gc0 = (int)(blockIdx.x & 7) * 8;

    float acc[2][8][4];
    #pragma unroll
    for (int mt = 0; mt < 2; ++mt)
        #pragma unroll
        for (int nt = 0; nt < 8; ++nt)
            #pragma unroll
            for (int r = 0; r < 4; ++r) acc[mt][nt][r] = 0.f;

    // ---- cp.async per-thread constants ----
    unsigned dstO[4];
    unsigned srcA[4], srcB[4];
    #pragma unroll
    for (int t = 0; t < 4; ++t) {
        int idx = tid + t * 256;               // 0..1023
        dstO[t] = SWZ((unsigned)idx * 16u);
        int m = idx >> 3, q = idx & 7;
        srcA[t] = (unsigned)(((gr0 + (m >> 3)) * XW + gc0 + (m & 7)) * (CIN * 2)) + q * 16;
        srcB[t] = (unsigned)(m * (CIN * 2)) + q * 16;   // m = n row for B
    }
    const size_t bxoff = (size_t)b * XH * XW * (CIN * 2);

    auto iter_bases = [&](int s, const char*& uA, const char*& uB) {
        int tap = s >> 3;
        int kc = s & 7;
        int dr = tap / 3, dc = tap - dr * 3;
        uA = (const char*)g_xh + bxoff + (size_t)((dr * XW + dc) * (CIN * 2)) + kc * (KC * 2);
        uB = (const char*)g_w + (size_t)tap * (COUT * CIN * 2)
             + (size_t)co0 * (CIN * 2) + kc * (KC * 2);
    };

    auto issue_copies = [&](int stage, int s) {
        const char *uA, *uB;
        iter_bases(s, uA, uB);
        unsigned sa = sbase + stage * STGB;
        unsigned sb = sa + 16384;
        #pragma unroll
        for (int t = 0; t < 4; ++t) cp16(sa + dstO[t], uA + srcA[t]);
        #pragma unroll
        for (int t = 0; t < 4; ++t) cp16(sb + dstO[t], uB + srcB[t]);
        cp_commit();
    };

    // ---- ldmatrix per-thread address components ----
    const int a_row[2] = { warp_m * 32 + 0 * 16 + (lane & 15),
                           warp_m * 32 + 1 * 16 + (lane & 15) };
    const int a_csel = lane >> 4;                     // 0/1
    int b_row[4];
    #pragma unroll
    for (int q = 0; q < 4; ++q)
        b_row[q] = warp_n * 64 + q * 16 + (((lane >> 4) & 1) << 3) + (lane & 7);
    const int b_csel = (lane >> 3) & 1;

    // prologue: iters 0,1 into stages 0,1
    issue_copies(0, 0);
    issue_copies(1, 1);

    for (int s = 0; s < NITER; ++s) {
        const int st = s % NSTG;
        cp_wait1();
        __syncthreads();

        if (s + 2 < NITER) issue_copies((s + 2) % NSTG, s + 2);
        else cp_commit();

        const unsigned sa = sbase + st * STGB;
        const unsigned sb = sa + 16384;

        #pragma unroll
        for (int ks = 0; ks < 4; ++ks) {
            unsigned af[2][4];
            #pragma unroll
            for (int mt = 0; mt < 2; ++mt) {
                int row = a_row[mt];
                unsigned addr = sa + row * 128 + (((2 * ks + a_csel) ^ (row & 7)) << 4);
                ldm_x4(af[mt][0], af[mt][1], af[mt][2], af[mt][3], addr);
            }
            unsigned bf[8][2];
            #pragma unroll
            for (int q = 0; q < 4; ++q) {
                int row = b_row[q];
                unsigned addr = sb + row * 128 + (((2 * ks + b_csel) ^ (row & 7)) << 4);
                unsigned r0, r1, r2, r3;
                ldm_x4(r0, r1, r2, r3, addr);
                bf[2 * q][0] = r0;  bf[2 * q][1] = r1;
                bf[2 * q + 1][0] = r2;  bf[2 * q + 1][1] = r3;
            }
            #pragma unroll
            for (int mt = 0; mt < 2; ++mt)
                #pragma unroll
                for (int nt = 0; nt < 8; ++nt)
                    mma16816(acc[mt][nt], af[mt], bf[nt]);
        }
    }

    // ================= epilogue: smem transpose -> coalesced demod store =====
    __syncthreads();
    float* smemD = (float*)(dyn_smem + ((1024 - (smem_u32(dyn_smem) & 1023)) & 1023));
    float* gsm = smemD + 128 * 132;
    if (tid < 128) gsm[tid] = g_g[b * COUT + co0 + tid];
    #pragma unroll
    for (int mt = 0; mt < 2; ++mt)
        #pragma unroll
        for (int nt = 0; nt < 8; ++nt) {
            int n = warp_n * 64 + nt * 8 + (lane & 3) * 2;
            int m = warp_m * 32 + mt * 16 + (lane >> 2);
            smemD[n * 132 + m]             = acc[mt][nt][0];
            smemD[(n + 1) * 132 + m]       = acc[mt][nt][1];
            smemD[n * 132 + m + 8]         = acc[mt][nt][2];
            smemD[(n + 1) * 132 + m + 8]   = acc[mt][nt][3];
        }
    __syncthreads();

    #pragma unroll 4
    for (int it = 0; it < 64; ++it) {
        int idx = tid + it * 256;       // 0..16383
        int n = idx >> 7;
        int m = idx & 127;
        int co = co0 + n;
        int h = gr0 + (m >> 3);
        int w = gc0 + (m & 7);
        out[(((size_t)b * COUT + co) * HDIM + h) * WDIM + w] = smemD[n * 132 + m] * gsm[n];
    }
}

extern "C" void kernel_launch(void* const* d_in, const int* in_sizes, int n_in,
                              void* d_out, int out_size) {
    const float* x          = (const float*)d_in[0];
    const float* style      = (const float*)d_in[1];
    const float* weight     = (const float*)d_in[2];
    const float* mod_weight = (const float*)d_in[3];
    const float* mod_bias   = (const float*)d_in[4];
    float* out = (float*)d_out;

    const long long conv_elems = (long long)BSZ * COUT * HDIM * WDIM;
    float* tail = (out_size >= conv_elems + BSZ * CIN) ? (out + conv_elems) : nullptr;

    cudaFuncSetAttribute(k_conv, cudaFuncAttributeMaxDynamicSharedMemorySize, SMEM_BYTES);

    k_prep0<<<1536, 256>>>(style, mod_weight, mod_bias, weight, tail);
    k_demod<<<(BSZ * COUT * 32) / 256, 256>>>();
    k_xprep<<<BSZ * HDIM, 256>>>(x);

    dim3 grid(32, COUT / NT, BSZ);   // (32, 4, 8)
    k_conv<<<grid, 256, SMEM_BYTES>>>(out);
}